// round 1
// baseline (speedup 1.0000x reference)
#include <cuda_runtime.h>
#include <cstdint>

// Conv2d direct: input (64,8,256,256) f32 NCHW, filter (8,8,3,3) OIHW,
// VALID, stride 1 -> out (64,8,254,254) f32.
//
// Strategy: output tile 64(w) x 32(h) x 8(M) per block, one n per block.
// Thread (tx,ty) computes column tx, rows ty*8..ty*8+7, all 8 M channels.
// M channels paired into f32x2 accumulators; math via fma.rn.f32x2 (FFMA2),
// which doubles FP32 throughput vs scalar FFMA on sm_103a.
// Input staged in SMEM 4 channels at a time (2 passes) to stay < 48KB static.

#define CONV_N 64
#define CONV_C 8
#define CONV_H 256
#define CONV_W 256
#define CONV_M 8
#define CONV_P 254
#define CONV_Q 254

#define TILE_W 64
#define TILE_H 32
#define RPT 8          // rows per thread
#define CPB 4          // channels per smem pass

__global__ __launch_bounds__(256, 2)
void Im2Col_Conv2d_6854767804820_kernel(const float* __restrict__ in,
                                        const float* __restrict__ filt,
                                        float* __restrict__ out)
{
    // SMEM: input halo tile for 4 channels + filter transposed [ (c*3+r)*3+s ][ m ]
    __shared__ float sIn[CPB][TILE_H + 2][TILE_W + 2];   // 4*34*66*4 = 35904 B
    __shared__ float sW[CONV_C * 9][CONV_M];             // 72*8*4    =  2304 B

    const int tx  = threadIdx.x;            // 0..63
    const int ty  = threadIdx.y;            // 0..3
    const int tid = ty * 64 + tx;

    const int col0 = blockIdx.x * TILE_W;   // 0,64,128,192
    const int row0 = blockIdx.y * TILE_H;   // 0..224
    const int n    = blockIdx.z;

    // ---- load filter, transposed so m is contiguous (LDS.64 => packed m-pair)
    // global filt layout: [m][c][r][s] -> f[m*72 + rem], rem = (c*3+r)*3+s
    for (int i = tid; i < CONV_M * CONV_C * 9; i += 256) {
        int m   = i / 72;
        int rem = i % 72;
        sW[rem][m] = filt[m * 72 + rem];
    }

    const float* inN = in + (size_t)n * CONV_C * CONV_H * CONV_W;

    // accumulators: 8 rows x 4 m-pairs, each a packed f32x2
    unsigned long long acc[RPT][4];
#pragma unroll
    for (int j = 0; j < RPT; j++)
#pragma unroll
        for (int p = 0; p < 4; p++) acc[j][p] = 0ull;

    const int rbase = ty * RPT;

    for (int cb = 0; cb < CONV_C / CPB; cb++) {
        __syncthreads();   // protect previous pass's tile until everyone is done

        // ---- stage 4 channels of the input halo tile: CPB * 34 * 66 floats
        for (int i = tid; i < CPB * (TILE_H + 2) * (TILE_W + 2); i += 256) {
            int col = i % (TILE_W + 2);
            int t   = i / (TILE_W + 2);
            int row = t % (TILE_H + 2);
            int cl  = t / (TILE_H + 2);
            int gr = row0 + row;
            int gc = col0 + col;
            float v = 0.0f;
            if (gr < CONV_H && gc < CONV_W)
                v = inN[((size_t)(cb * CPB + cl) * CONV_H + gr) * CONV_W + gc];
            sIn[cl][row][col] = v;
        }
        __syncthreads();

        for (int cl = 0; cl < CPB; cl++) {
            const int c = cb * CPB + cl;

            // register-cache the 10x3 input window this thread needs
            float x[RPT + 2][3];
#pragma unroll
            for (int j = 0; j < RPT + 2; j++)
#pragma unroll
                for (int s = 0; s < 3; s++)
                    x[j][s] = sIn[cl][rbase + j][tx + s];

#pragma unroll
            for (int r = 0; r < 3; r++) {
#pragma unroll
                for (int s = 0; s < 3; s++) {
                    // packed m-pair weights (broadcast LDS.64)
                    unsigned long long w2[4];
                    const float* wrow = &sW[(c * 3 + r) * 3 + s][0];
#pragma unroll
                    for (int p = 0; p < 4; p++)
                        w2[p] = *reinterpret_cast<const unsigned long long*>(wrow + 2 * p);

#pragma unroll
                    for (int j = 0; j < RPT; j++) {
                        float xv = x[j + r][s];
                        unsigned long long x2;
                        asm("mov.b64 %0, {%1, %1};" : "=l"(x2) : "f"(xv));
#pragma unroll
                        for (int p = 0; p < 4; p++) {
                            asm("fma.rn.f32x2 %0, %1, %2, %0;"
                                : "+l"(acc[j][p])
                                : "l"(x2), "l"(w2[p]));
                        }
                    }
                }
            }
        }
    }

    // ---- store: out[n][m][orow][ocol]
    const int ocol = col0 + tx;
    if (ocol < CONV_Q) {
        float* outN = out + (size_t)n * CONV_M * CONV_P * CONV_Q;
#pragma unroll
        for (int j = 0; j < RPT; j++) {
            int orow = row0 + rbase + j;
            if (orow < CONV_P) {
#pragma unroll
                for (int p = 0; p < 4; p++) {
                    unsigned int lo = (unsigned int)(acc[j][p] & 0xffffffffull);
                    unsigned int hi = (unsigned int)(acc[j][p] >> 32);
                    outN[((size_t)(2 * p)     * CONV_P + orow) * CONV_Q + ocol] = __uint_as_float(lo);
                    outN[((size_t)(2 * p + 1) * CONV_P + orow) * CONV_Q + ocol] = __uint_as_float(hi);
                }
            }
        }
    }
}

extern "C" void kernel_launch(void* const* d_in, const int* in_sizes, int n_in,
                              void* d_out, int out_size)
{
    const float* input  = (const float*)d_in[0];   // (64,8,256,256)
    const float* filter = (const float*)d_in[1];   // (8,8,3,3)
    float* output = (float*)d_out;                 // (64,8,254,254)

    dim3 block(64, 4, 1);
    dim3 grid((CONV_Q + TILE_W - 1) / TILE_W,      // 4
              (CONV_P + TILE_H - 1) / TILE_H,      // 8
              CONV_N);                             // 64
    Im2Col_Conv2d_6854767804820_kernel<<<grid, block>>>(input, filter, output);
}